// round 3
// baseline (speedup 1.0000x reference)
#include <cuda_runtime.h>
#include <cuda_bf16.h>

// BBAStar: 8-connected grid shortest path, B=128, 32x32 grids.
// R2: register-band relaxation. 256 threads / CTA, warp w owns rows 4w..4w+3
// (lane = column, dist in registers). Horizontal neighbors via shfl snapshot,
// vertical Gauss-Seidel with alternating sweep direction; cross-band rows via
// volatile smem write-through. Monotone racy relaxation converges to the exact
// float fixed point of the reference's 1024 Jacobi sweeps (schedule-independent).
// Backtrack uses a precomputed per-cell argmin-neighbor direction (exact OFFS
// first-occurrence tie-break), so the serial chain is 1 LDS per step.

#define BN 128
#define HN 32
#define WN 32
#define PW 34
#define INF_F 1000000000.0f
#define EPS_F 1e-6f
#define KPASS 6

__device__ __forceinline__ float shlf(float v, int c) {
    float t = __shfl_up_sync(0xffffffffu, v, 1);
    return (c == 0) ? INF_F : t;
}
__device__ __forceinline__ float shrf(float v, int c) {
    float t = __shfl_down_sync(0xffffffffu, v, 1);
    return (c == 31) ? INF_F : t;
}
__device__ __forceinline__ float min8f(float a, float b, float c, float d,
                                       float e, float f, float g, float h) {
    return fminf(fminf(fminf(a, b), fminf(c, d)),
                 fminf(fminf(e, f), fminf(g, h)));
}
// OFFS-order first-occurrence argmin (strict '<'), matching jnp.argmin.
__device__ __forceinline__ int pick8(float a0, float a1, float a2, float a3,
                                     float a4, float a5, float a6, float a7) {
    float bb = a0; int bd = 0;
    if (a1 < bb) { bb = a1; bd = 1; }
    if (a2 < bb) { bb = a2; bd = 2; }
    if (a3 < bb) { bb = a3; bd = 3; }
    if (a4 < bb) { bb = a4; bd = 4; }
    if (a5 < bb) { bb = a5; bd = 5; }
    if (a6 < bb) { bb = a6; bd = 6; }
    if (a7 < bb) { bb = a7; bd = 7; }
    return bd;
}

__global__ void __launch_bounds__(256, 1)
bba_kernel(const float* __restrict__ weights,
           const int*   __restrict__ source,
           const int*   __restrict__ target,
           float*       __restrict__ out)
{
    __shared__ float dist[PW * PW];     // 34x34, INF-padded border
    __shared__ int   nbr[HN * WN];      // argmin-neighbor direction per cell
    __shared__ int   changed;
    volatile float* vdist = dist;

    const int b   = blockIdx.x;
    const int tid = threadIdx.x;
    const int w   = tid >> 5;           // warp = band index (0..7)
    const int c   = tid & 31;           // lane = column
    const int r0  = 4 * w;              // first global row of band
    const int pc  = c + 1;              // padded column

    // Zero the poisoned output slice.
    #pragma unroll
    for (int i = 0; i < 4; ++i) out[b * 1024 + i * 256 + tid] = 0.0f;

    for (int i = tid; i < PW * PW; i += 256) dist[i] = INF_F;
    if (tid == 0) changed = 0;

    const float* wb = weights + b * 1024;
    const float w0 = wb[(r0 + 0) * 32 + c] + EPS_F;
    const float w1 = wb[(r0 + 1) * 32 + c] + EPS_F;
    const float w2 = wb[(r0 + 2) * 32 + c] + EPS_F;
    const float w3 = wb[(r0 + 3) * 32 + c] + EPS_F;

    const int sr = source[2 * b + 0];
    const int sc = source[2 * b + 1];
    const int tr = target[2 * b + 0];
    const int tc = target[2 * b + 1];

    float d0 = INF_F, d1 = INF_F, d2 = INF_F, d3 = INF_F;

    __syncthreads();
    if (c == sc && sr >= r0 && sr < r0 + 4) {
        if (sr == r0 + 0) { d0 = w0; vdist[(r0 + 1) * PW + pc] = d0; }
        if (sr == r0 + 1) { d1 = w1; vdist[(r0 + 2) * PW + pc] = d1; }
        if (sr == r0 + 2) { d2 = w2; vdist[(r0 + 3) * PW + pc] = d2; }
        if (sr == r0 + 3) { d3 = w3; vdist[(r0 + 4) * PW + pc] = d3; }
    }
    __syncthreads();

    // Epoch-based relaxation to the float fixed point.
    for (;;) {
        bool any = false;
        #pragma unroll 1
        for (int k = 0; k < KPASS; ++k) {
            // Cross-band rows (padded row r0 and r0+5; border rows give INF).
            float X  = vdist[(r0 + 0) * PW + pc];
            float Y  = vdist[(r0 + 5) * PW + pc];
            // Horizontal snapshots (Jacobi for diagonals/sides).
            float XL = shlf(X,  c), XR = shrf(X,  c);
            float L0 = shlf(d0, c), R0 = shrf(d0, c);
            float L1 = shlf(d1, c), R1 = shrf(d1, c);
            float L2 = shlf(d2, c), R2 = shrf(d2, c);
            float L3 = shlf(d3, c), R3 = shrf(d3, c);
            float YL = shlf(Y,  c), YR = shrf(Y,  c);
            float nm, v;
            if ((k & 1) == 0) {
                // Down sweep: straight-up center uses updated register.
                nm = min8f(XL, X,  XR, L0, R0, L1, d1, R1);
                v = w0 + nm; if (v < d0) { d0 = v; vdist[(r0 + 1) * PW + pc] = v; any = true; }
                nm = min8f(L0, d0, R0, L1, R1, L2, d2, R2);
                v = w1 + nm; if (v < d1) { d1 = v; vdist[(r0 + 2) * PW + pc] = v; any = true; }
                nm = min8f(L1, d1, R1, L2, R2, L3, d3, R3);
                v = w2 + nm; if (v < d2) { d2 = v; vdist[(r0 + 3) * PW + pc] = v; any = true; }
                nm = min8f(L2, d2, R2, L3, R3, YL, Y,  YR);
                v = w3 + nm; if (v < d3) { d3 = v; vdist[(r0 + 4) * PW + pc] = v; any = true; }
            } else {
                // Up sweep: straight-down center uses updated register.
                nm = min8f(L2, d2, R2, L3, R3, YL, Y,  YR);
                v = w3 + nm; if (v < d3) { d3 = v; vdist[(r0 + 4) * PW + pc] = v; any = true; }
                nm = min8f(L1, d1, R1, L2, R2, L3, d3, R3);
                v = w2 + nm; if (v < d2) { d2 = v; vdist[(r0 + 3) * PW + pc] = v; any = true; }
                nm = min8f(L0, d0, R0, L1, R1, L2, d2, R2);
                v = w1 + nm; if (v < d1) { d1 = v; vdist[(r0 + 2) * PW + pc] = v; any = true; }
                nm = min8f(XL, X,  XR, L0, R0, L1, d1, R1);
                v = w0 + nm; if (v < d0) { d0 = v; vdist[(r0 + 1) * PW + pc] = v; any = true; }
            }
        }
        if (any) changed = 1;            // benign race
        __syncthreads();                 // epoch writes + flag visible
        int c0 = changed;
        __syncthreads();                 // all reads done before reset
        if (!c0) break;                  // zero-change consistent epoch => fixed point
        if (tid == 0) changed = 0;
        __syncthreads();
    }

    // Precompute argmin-neighbor direction per cell (parallel), OFFS order:
    // (-1,-1),(-1,0),(-1,1),(0,-1),(0,1),(1,-1),(1,0),(1,1).
    {
        float X  = vdist[(r0 + 0) * PW + pc];
        float Y  = vdist[(r0 + 5) * PW + pc];
        float XL = shlf(X,  c), XR = shrf(X,  c);
        float L0 = shlf(d0, c), R0 = shrf(d0, c);
        float L1 = shlf(d1, c), R1 = shrf(d1, c);
        float L2 = shlf(d2, c), R2 = shrf(d2, c);
        float L3 = shlf(d3, c), R3 = shrf(d3, c);
        float YL = shlf(Y,  c), YR = shrf(Y,  c);
        nbr[(r0 + 0) * 32 + c] = pick8(XL, X,  XR, L0, R0, L1, d1, R1);
        nbr[(r0 + 1) * 32 + c] = pick8(L0, d0, R0, L1, R1, L2, d2, R2);
        nbr[(r0 + 2) * 32 + c] = pick8(L1, d1, R1, L2, R2, L3, d3, R3);
        nbr[(r0 + 3) * 32 + c] = pick8(L2, d2, R2, L3, R3, YL, Y,  YR);
    }
    __syncthreads();

    // Serial backtrack: follow precomputed directions (strictly decreasing
    // dist ensures termination at the source, <= 1023 steps).
    if (tid == 0) {
        const int drs[8] = {-1, -1, -1,  0, 0,  1, 1, 1};
        const int dcs[8] = {-1,  0,  1, -1, 1, -1, 0, 1};
        int cr = tr, cc = tc;
        float* o = out + b * 1024;
        for (int step = 0; step < 1024; ++step) {
            o[cr * 32 + cc] = 1.0f;
            if (cr == sr && cc == sc) break;
            int k = nbr[cr * 32 + cc];
            cr += drs[k];
            cc += dcs[k];
        }
    }
}

extern "C" void kernel_launch(void* const* d_in, const int* in_sizes, int n_in,
                              void* d_out, int out_size)
{
    const float* weights = (const float*)d_in[0];
    const int*   source  = (const int*)d_in[1];
    const int*   target  = (const int*)d_in[2];
    float*       out     = (float*)d_out;

    bba_kernel<<<BN, 256>>>(weights, source, target, out);
}

// round 4
// speedup vs baseline: 1.1366x; 1.1366x over previous
#include <cuda_runtime.h>
#include <cuda_bf16.h>

// BBAStar: 8-connected grid shortest path, B=128, 32x32.
// R3: orientation-alternating Gauss-Seidel sweeps (fast-sweeping style).
// V phase: warp owns 4 rows (lane=col), GS down+up sweeps with diagonal
// propagation (shfl of freshly updated row). H phase: warp owns 4 cols
// (lane=row), GS right+left. Registers reloaded from smem dist each phase.
// Monotone relaxation => converges to the exact float fixed point of the
// reference's 1024 Jacobi sweeps regardless of schedule. Termination via a
// zero-change super-epoch behind barriers. Backtrack via precomputed argmin
// directions (exact OFFS first-occurrence tie-break).

#define BN 128
#define ST 35              // smem row stride (odd => conflict-free both axes)
#define INF_F 1000000000.0f
#define EPS_F 1e-6f
#define KP 2               // fwd+bwd sweep pairs per phase

__device__ __forceinline__ float shl(float v, int lane) {
    float t = __shfl_up_sync(0xffffffffu, v, 1);
    return (lane == 0) ? INF_F : t;
}
__device__ __forceinline__ float shr(float v, int lane) {
    float t = __shfl_down_sync(0xffffffffu, v, 1);
    return (lane == 31) ? INF_F : t;
}
__device__ __forceinline__ float min8f(float a, float b, float c, float d,
                                       float e, float f, float g, float h) {
    return fminf(fminf(fminf(a, b), fminf(c, d)),
                 fminf(fminf(e, f), fminf(g, h)));
}
__device__ __forceinline__ int pick8(float a0, float a1, float a2, float a3,
                                     float a4, float a5, float a6, float a7) {
    float bb = a0; int bd = 0;
    if (a1 < bb) { bb = a1; bd = 1; }
    if (a2 < bb) { bb = a2; bd = 2; }
    if (a3 < bb) { bb = a3; bd = 3; }
    if (a4 < bb) { bb = a4; bd = 4; }
    if (a5 < bb) { bb = a5; bd = 5; }
    if (a6 < bb) { bb = a6; bd = 6; }
    if (a7 < bb) { bb = a7; bd = 7; }
    return bd;
}

// One GS fwd+bwd sweep pair over 4 owned cells per lane.
// Own cell k lives at vd[i0 + k*di]; "prev" side at vd[ix], "next" at vd[iy].
// Diagonal-inclusive GS: freshly updated line is shfl'd before the next line.
__device__ __forceinline__ void sweep_pair(volatile float* vd,
                                           const float w[4], float d[4],
                                           int i0, int di, int ix, int iy,
                                           int lane, bool& any)
{
    // forward sweep
    {
        float X = vd[ix], Y = vd[iy];
        float p = X, pl = shl(X, lane), pr = shr(X, lane);
        #pragma unroll
        for (int i = 0; i < 4; ++i) {
            float nx = (i < 3) ? d[i + 1] : Y;
            float nl = shl(nx, lane),  nr = shr(nx, lane);
            float cl = shl(d[i], lane), cr = shr(d[i], lane);
            float v = w[i] + min8f(pl, p, pr, cl, cr, nl, nx, nr);
            if (v < d[i]) { d[i] = v; vd[i0 + i * di] = v; any = true; }
            p = d[i]; pl = shl(p, lane); pr = shr(p, lane);
        }
    }
    // backward sweep
    {
        float X = vd[ix], Y = vd[iy];
        float p = Y, pl = shl(Y, lane), pr = shr(Y, lane);
        #pragma unroll
        for (int i = 3; i >= 0; --i) {
            float nx = (i > 0) ? d[i - 1] : X;
            float nl = shl(nx, lane),  nr = shr(nx, lane);
            float cl = shl(d[i], lane), cr = shr(d[i], lane);
            float v = w[i] + min8f(nl, nx, nr, cl, cr, pl, p, pr);
            if (v < d[i]) { d[i] = v; vd[i0 + i * di] = v; any = true; }
            p = d[i]; pl = shl(p, lane); pr = shr(p, lane);
        }
    }
}

__global__ void __launch_bounds__(256, 1)
bba_kernel(const float* __restrict__ weights,
           const int*   __restrict__ source,
           const int*   __restrict__ target,
           float*       __restrict__ out)
{
    __shared__ float dist[34 * ST];     // padded 34x34 grid, stride 35
    __shared__ float wsh[32][33];       // weights, conflict-free both axes
    __shared__ int   nbr[1024];
    __shared__ int   changed;
    volatile float* vd = dist;

    const int b    = blockIdx.x;
    const int tid  = threadIdx.x;
    const int wpid = tid >> 5;          // warp id 0..7
    const int lane = tid & 31;
    const int r0   = 4 * wpid;          // V phase: first row of band
    const int c0   = 4 * wpid;          // H phase: first col of band

    // Zero poisoned output slice.
    #pragma unroll
    for (int i = 0; i < 4; ++i) out[b * 1024 + i * 256 + tid] = 0.0f;

    for (int i = tid; i < 34 * ST; i += 256) dist[i] = INF_F;
    if (tid == 0) changed = 0;

    // Weights (+EPS), V-layout load, stash in smem for H-layout reads.
    const float* wb = weights + b * 1024;
    float wv[4], wh[4];
    #pragma unroll
    for (int i = 0; i < 4; ++i) {
        wv[i] = wb[(r0 + i) * 32 + lane] + EPS_F;
        wsh[r0 + i][lane] = wv[i];
    }

    const int sr = source[2 * b + 0];
    const int sc = source[2 * b + 1];
    const int tr = target[2 * b + 0];
    const int tc = target[2 * b + 1];

    __syncthreads();

    #pragma unroll
    for (int i = 0; i < 4; ++i) wh[i] = wsh[lane][c0 + i];

    if (tid == 0) dist[(sr + 1) * ST + (sc + 1)] = wsh[sr][sc];
    __syncthreads();

    // Indices for both orientations.
    const int v_i0 = (r0 + 1) * ST + (lane + 1);   // own cells, step ST
    const int v_ix = (r0 + 0) * ST + (lane + 1);   // row above band
    const int v_iy = (r0 + 5) * ST + (lane + 1);   // row below band
    const int h_i0 = (lane + 1) * ST + (c0 + 1);   // own cells, step 1
    const int h_ix = (lane + 1) * ST + (c0 + 0);   // col left of band
    const int h_iy = (lane + 1) * ST + (c0 + 5);   // col right of band

    float d[4];

    for (;;) {
        bool any = false;

        // V phase
        #pragma unroll
        for (int i = 0; i < 4; ++i) d[i] = vd[v_i0 + i * ST];
        #pragma unroll 1
        for (int k = 0; k < KP; ++k)
            sweep_pair(vd, wv, d, v_i0, ST, v_ix, v_iy, lane, any);

        __syncthreads();                 // V writes visible before H phase

        // H phase
        #pragma unroll
        for (int i = 0; i < 4; ++i) d[i] = vd[h_i0 + i];
        #pragma unroll 1
        for (int k = 0; k < KP; ++k)
            sweep_pair(vd, wh, d, h_i0, 1, h_ix, h_iy, lane, any);

        if (any) changed = 1;            // benign race
        __syncthreads();
        int c0f = changed;
        __syncthreads();
        if (!c0f) break;                 // zero-change super-epoch => fixed pt
        if (tid == 0) changed = 0;
        __syncthreads();
    }

    // Parallel argmin-neighbor directions (V layout), OFFS order:
    // (-1,-1),(-1,0),(-1,1),(0,-1),(0,1),(1,-1),(1,0),(1,1)
    {
        #pragma unroll
        for (int i = 0; i < 4; ++i) d[i] = vd[v_i0 + i * ST];
        float X  = vd[v_ix], Y = vd[v_iy];
        float XL = shl(X, lane),   XR = shr(X, lane);
        float L0 = shl(d[0], lane), R0 = shr(d[0], lane);
        float L1 = shl(d[1], lane), R1 = shr(d[1], lane);
        float L2 = shl(d[2], lane), R2 = shr(d[2], lane);
        float L3 = shl(d[3], lane), R3 = shr(d[3], lane);
        float YL = shl(Y, lane),   YR = shr(Y, lane);
        nbr[(r0 + 0) * 32 + lane] = pick8(XL, X,    XR, L0, R0, L1, d[1], R1);
        nbr[(r0 + 1) * 32 + lane] = pick8(L0, d[0], R0, L1, R1, L2, d[2], R2);
        nbr[(r0 + 2) * 32 + lane] = pick8(L1, d[1], R1, L2, R2, L3, d[3], R3);
        nbr[(r0 + 3) * 32 + lane] = pick8(L2, d[2], R2, L3, R3, YL, Y,    YR);
    }
    __syncthreads();

    // Serial backtrack: follow precomputed directions.
    if (tid == 0) {
        const int drs[8] = {-1, -1, -1,  0, 0,  1, 1, 1};
        const int dcs[8] = {-1,  0,  1, -1, 1, -1, 0, 1};
        int cr = tr, cc = tc;
        float* o = out + b * 1024;
        for (int step = 0; step < 1024; ++step) {
            o[cr * 32 + cc] = 1.0f;
            if (cr == sr && cc == sc) break;
            int k = nbr[cr * 32 + cc];
            cr += drs[k];
            cc += dcs[k];
        }
    }
}

extern "C" void kernel_launch(void* const* d_in, const int* in_sizes, int n_in,
                              void* d_out, int out_size)
{
    const float* weights = (const float*)d_in[0];
    const int*   source  = (const int*)d_in[1];
    const int*   target  = (const int*)d_in[2];
    float*       out     = (float*)d_out;

    bba_kernel<<<BN, 256>>>(weights, source, target, out);
}